// round 1
// baseline (speedup 1.0000x reference)
#include <cuda_runtime.h>

// All-pairs N-body gravity forces.
//   forces[i] = sum_j m[j] * (p[j]-p[i]) / (|p[j]-p[i]|^2 + eps^2)^1.5
// N = 8192, fp32. Compute-bound: ~12 fma-pipe ops + 1 MUFU.RSQ per pair.

#ifndef BLOCK
#define BLOCK 256
#endif
#define JCHUNK 512
#define EPS2 0.0001f   // SOFTENING^2 = 0.01^2

__global__ void zero_out_kernel(float* __restrict__ out, int n) {
    int i = blockIdx.x * blockDim.x + threadIdx.x;
    if (i < n) out[i] = 0.0f;
}

__global__ __launch_bounds__(BLOCK)
void nbody_forces_kernel(const float* __restrict__ pos,
                         const float* __restrict__ mass,
                         float* __restrict__ out,
                         int n) {
    __shared__ float4 sj[JCHUNK];

    const int i     = blockIdx.x * BLOCK + threadIdx.x;
    const int jbase = blockIdx.y * JCHUNK;

    // Stage this block's j-chunk into shared as float4{x,y,z,m}.
    for (int t = threadIdx.x; t < JCHUNK; t += BLOCK) {
        int j = jbase + t;
        sj[t] = make_float4(pos[3 * j + 0], pos[3 * j + 1], pos[3 * j + 2],
                            mass[j]);
    }
    __syncthreads();

    const float xi = pos[3 * i + 0];
    const float yi = pos[3 * i + 1];
    const float zi = pos[3 * i + 2];

    float ax = 0.0f, ay = 0.0f, az = 0.0f;

#pragma unroll 8
    for (int t = 0; t < JCHUNK; ++t) {
        float4 p = sj[t];                 // broadcast LDS.128
        float dx = p.x - xi;
        float dy = p.y - yi;
        float dz = p.z - zi;
        float r2 = fmaf(dx, dx, fmaf(dy, dy, fmaf(dz, dz, EPS2)));
        float inv  = rsqrtf(r2);          // MUFU.RSQ (~2 ulp, fine for 1e-3)
        float inv3 = inv * inv * inv;
        float s    = p.w * inv3;          // G = 1
        ax = fmaf(s, dx, ax);
        ay = fmaf(s, dy, ay);
        az = fmaf(s, dz, az);
    }

    // Accumulate this j-segment's partial force. Cross-block contention only
    // (16 writers per address) — REDG handles it cheaply.
    atomicAdd(&out[3 * i + 0], ax);
    atomicAdd(&out[3 * i + 1], ay);
    atomicAdd(&out[3 * i + 2], az);
}

extern "C" void kernel_launch(void* const* d_in, const int* in_sizes, int n_in,
                              void* d_out, int out_size) {
    const float* pos  = (const float*)d_in[0];   // [N,3] float32
    const float* mass = (const float*)d_in[1];   // [N]   float32
    float* out = (float*)d_out;                  // [N,3] float32

    const int n = in_sizes[0] / 3;               // 8192

    // d_out is poisoned 0xAA — zero it before atomic accumulation.
    zero_out_kernel<<<(out_size + 255) / 256, 256>>>(out, out_size);

    dim3 grid(n / BLOCK, n / JCHUNK);            // 32 x 16 = 512 CTAs
    nbody_forces_kernel<<<grid, BLOCK>>>(pos, mass, out, n);
}

// round 2
// speedup vs baseline: 1.1296x; 1.1296x over previous
#include <cuda_runtime.h>

// All-pairs N-body gravity, packed f32x2 formulation (sm_103a FFMA2).
// Two j-bodies per lane per iteration: shared memory holds the j-chunk as
// pair-packed b64 words ({x_j, x_{j+1}} etc.) so LDS.64 broadcast feeds
// fma.rn.f32x2 directly. Halves fma-pipe work vs scalar: 6 ops/pair.

#define BLOCK  256
#define JCHUNK 256
#define JP     (JCHUNK / 2)
#define EPS2   0.0001f   // SOFTENING^2

typedef unsigned long long u64;

__device__ __forceinline__ u64 pack2(float lo, float hi) {
    u64 r;
    asm("mov.b64 %0, {%1, %2};" : "=l"(r)
        : "r"(__float_as_uint(lo)), "r"(__float_as_uint(hi)));
    return r;
}
__device__ __forceinline__ void unpack2(u64 v, float& lo, float& hi) {
    unsigned a, b;
    asm("mov.b64 {%0, %1}, %2;" : "=r"(a), "=r"(b) : "l"(v));
    lo = __uint_as_float(a);
    hi = __uint_as_float(b);
}
__device__ __forceinline__ u64 f2add(u64 a, u64 b) {
    u64 r; asm("add.rn.f32x2 %0, %1, %2;" : "=l"(r) : "l"(a), "l"(b)); return r;
}
__device__ __forceinline__ u64 f2mul(u64 a, u64 b) {
    u64 r; asm("mul.rn.f32x2 %0, %1, %2;" : "=l"(r) : "l"(a), "l"(b)); return r;
}
__device__ __forceinline__ u64 f2fma(u64 a, u64 b, u64 c) {
    u64 r; asm("fma.rn.f32x2 %0, %1, %2, %3;"
               : "=l"(r) : "l"(a), "l"(b), "l"(c)); return r;
}

__global__ void zero_out_kernel(float* __restrict__ out, int n) {
    int i = blockIdx.x * blockDim.x + threadIdx.x;
    if (i < n) out[i] = 0.0f;
}

__global__ __launch_bounds__(BLOCK)
void nbody_forces_kernel(const float* __restrict__ pos,
                         const float* __restrict__ mass,
                         float* __restrict__ out) {
    // Pair-packed SoA: word t holds bodies {jbase+2t, jbase+2t+1}.
    __shared__ u64 sx[JP], sy[JP], sz[JP], sm[JP];

    const int i     = blockIdx.x * BLOCK + threadIdx.x;
    const int jbase = blockIdx.y * JCHUNK;

    for (int t = threadIdx.x; t < JCHUNK; t += BLOCK) {
        int j = jbase + t;
        ((float*)sx)[t] = pos[3 * j + 0];
        ((float*)sy)[t] = pos[3 * j + 1];
        ((float*)sz)[t] = pos[3 * j + 2];
        ((float*)sm)[t] = mass[j];
    }
    __syncthreads();

    const float xi = pos[3 * i + 0];
    const float yi = pos[3 * i + 1];
    const float zi = pos[3 * i + 2];

    const u64 nxi2  = pack2(-xi, -xi);
    const u64 nyi2  = pack2(-yi, -yi);
    const u64 nzi2  = pack2(-zi, -zi);
    const u64 eps22 = pack2(EPS2, EPS2);

    u64 ax2 = 0ull, ay2 = 0ull, az2 = 0ull;   // {0.0f, 0.0f}

#pragma unroll 4
    for (int t = 0; t < JP; ++t) {
        u64 px = sx[t];                        // LDS.64 broadcast
        u64 py = sy[t];
        u64 pz = sz[t];
        u64 pm = sm[t];

        u64 dx = f2add(px, nxi2);
        u64 dy = f2add(py, nyi2);
        u64 dz = f2add(pz, nzi2);

        u64 r2 = f2fma(dx, dx, f2fma(dy, dy, f2fma(dz, dz, eps22)));

        float rlo, rhi;
        unpack2(r2, rlo, rhi);
        u64 inv  = pack2(rsqrtf(rlo), rsqrtf(rhi));   // 2x MUFU.RSQ
        u64 inv2 = f2mul(inv, inv);
        u64 inv3 = f2mul(inv2, inv);
        u64 s    = f2mul(pm, inv3);            // G = 1

        ax2 = f2fma(s, dx, ax2);
        ay2 = f2fma(s, dy, ay2);
        az2 = f2fma(s, dz, az2);
    }

    float l, h;
    unpack2(ax2, l, h); float ax = l + h;
    unpack2(ay2, l, h); float ay = l + h;
    unpack2(az2, l, h); float az = l + h;

    atomicAdd(&out[3 * i + 0], ax);
    atomicAdd(&out[3 * i + 1], ay);
    atomicAdd(&out[3 * i + 2], az);
}

extern "C" void kernel_launch(void* const* d_in, const int* in_sizes, int n_in,
                              void* d_out, int out_size) {
    const float* pos  = (const float*)d_in[0];   // [N,3] float32
    const float* mass = (const float*)d_in[1];   // [N]   float32
    float* out = (float*)d_out;                  // [N,3] float32

    const int n = in_sizes[0] / 3;               // 8192

    zero_out_kernel<<<(out_size + 255) / 256, 256>>>(out, out_size);

    dim3 grid(n / BLOCK, n / JCHUNK);            // 32 x 32 = 1024 CTAs
    nbody_forces_kernel<<<grid, BLOCK>>>(pos, mass, out);
}

// round 3
// speedup vs baseline: 1.2034x; 1.0654x over previous
#include <cuda_runtime.h>

// All-pairs N-body gravity, packed f32x2 + 2 i-bodies per thread.
// f32x2 halves fma-pipe work (6 ops/pair); IPT=2 doubles independent
// dependency chains per warp to hide MUFU(16cyc)/pack-unpack latency that
// round 2 exposed (issue% fell 83->59).

#define BLOCK  128
#define IPT    2
#define JCHUNK 256
#define JP     (JCHUNK / 2)
#define EPS2   0.0001f   // SOFTENING^2

typedef unsigned long long u64;

__device__ __forceinline__ u64 pack2(float lo, float hi) {
    u64 r;
    asm("mov.b64 %0, {%1, %2};" : "=l"(r)
        : "r"(__float_as_uint(lo)), "r"(__float_as_uint(hi)));
    return r;
}
__device__ __forceinline__ void unpack2(u64 v, float& lo, float& hi) {
    unsigned a, b;
    asm("mov.b64 {%0, %1}, %2;" : "=r"(a), "=r"(b) : "l"(v));
    lo = __uint_as_float(a);
    hi = __uint_as_float(b);
}
__device__ __forceinline__ u64 f2add(u64 a, u64 b) {
    u64 r; asm("add.rn.f32x2 %0, %1, %2;" : "=l"(r) : "l"(a), "l"(b)); return r;
}
__device__ __forceinline__ u64 f2mul(u64 a, u64 b) {
    u64 r; asm("mul.rn.f32x2 %0, %1, %2;" : "=l"(r) : "l"(a), "l"(b)); return r;
}
__device__ __forceinline__ u64 f2fma(u64 a, u64 b, u64 c) {
    u64 r; asm("fma.rn.f32x2 %0, %1, %2, %3;"
               : "=l"(r) : "l"(a), "l"(b), "l"(c)); return r;
}

__global__ void zero_out_kernel(float* __restrict__ out, int n) {
    int i = blockIdx.x * blockDim.x + threadIdx.x;
    if (i < n) out[i] = 0.0f;
}

__global__ __launch_bounds__(BLOCK, 6)
void nbody_forces_kernel(const float* __restrict__ pos,
                         const float* __restrict__ mass,
                         float* __restrict__ out) {
    // Pair-packed SoA: word t holds bodies {jbase+2t, jbase+2t+1}.
    __shared__ u64 sx[JP], sy[JP], sz[JP], sm[JP];

    const int i0    = blockIdx.x * (BLOCK * IPT) + threadIdx.x;
    const int i1    = i0 + BLOCK;
    const int jbase = blockIdx.y * JCHUNK;

    for (int t = threadIdx.x; t < JCHUNK; t += BLOCK) {
        int j = jbase + t;
        ((float*)sx)[t] = pos[3 * j + 0];
        ((float*)sy)[t] = pos[3 * j + 1];
        ((float*)sz)[t] = pos[3 * j + 2];
        ((float*)sm)[t] = mass[j];
    }
    __syncthreads();

    const u64 nx0 = pack2(-pos[3 * i0 + 0], -pos[3 * i0 + 0]);
    const u64 ny0 = pack2(-pos[3 * i0 + 1], -pos[3 * i0 + 1]);
    const u64 nz0 = pack2(-pos[3 * i0 + 2], -pos[3 * i0 + 2]);
    const u64 nx1 = pack2(-pos[3 * i1 + 0], -pos[3 * i1 + 0]);
    const u64 ny1 = pack2(-pos[3 * i1 + 1], -pos[3 * i1 + 1]);
    const u64 nz1 = pack2(-pos[3 * i1 + 2], -pos[3 * i1 + 2]);
    const u64 eps22 = pack2(EPS2, EPS2);

    u64 ax0 = 0ull, ay0 = 0ull, az0 = 0ull;
    u64 ax1 = 0ull, ay1 = 0ull, az1 = 0ull;

#pragma unroll 4
    for (int t = 0; t < JP; ++t) {
        const u64 px = sx[t];              // LDS.64 broadcast, feeds 4 pairs
        const u64 py = sy[t];
        const u64 pz = sz[t];
        const u64 pm = sm[t];

        // chain 0
        u64 dx0 = f2add(px, nx0);
        u64 dy0 = f2add(py, ny0);
        u64 dz0 = f2add(pz, nz0);
        // chain 1 (independent — interleaves with chain 0's stalls)
        u64 dx1 = f2add(px, nx1);
        u64 dy1 = f2add(py, ny1);
        u64 dz1 = f2add(pz, nz1);

        u64 r20 = f2fma(dx0, dx0, f2fma(dy0, dy0, f2fma(dz0, dz0, eps22)));
        u64 r21 = f2fma(dx1, dx1, f2fma(dy1, dy1, f2fma(dz1, dz1, eps22)));

        float a, b;
        unpack2(r20, a, b);
        u64 inv0 = pack2(rsqrtf(a), rsqrtf(b));
        unpack2(r21, a, b);
        u64 inv1 = pack2(rsqrtf(a), rsqrtf(b));

        u64 s0 = f2mul(pm, f2mul(f2mul(inv0, inv0), inv0));
        u64 s1 = f2mul(pm, f2mul(f2mul(inv1, inv1), inv1));

        ax0 = f2fma(s0, dx0, ax0);
        ay0 = f2fma(s0, dy0, ay0);
        az0 = f2fma(s0, dz0, az0);
        ax1 = f2fma(s1, dx1, ax1);
        ay1 = f2fma(s1, dy1, ay1);
        az1 = f2fma(s1, dz1, az1);
    }

    float l, h;
    unpack2(ax0, l, h); atomicAdd(&out[3 * i0 + 0], l + h);
    unpack2(ay0, l, h); atomicAdd(&out[3 * i0 + 1], l + h);
    unpack2(az0, l, h); atomicAdd(&out[3 * i0 + 2], l + h);
    unpack2(ax1, l, h); atomicAdd(&out[3 * i1 + 0], l + h);
    unpack2(ay1, l, h); atomicAdd(&out[3 * i1 + 1], l + h);
    unpack2(az1, l, h); atomicAdd(&out[3 * i1 + 2], l + h);
}

extern "C" void kernel_launch(void* const* d_in, const int* in_sizes, int n_in,
                              void* d_out, int out_size) {
    const float* pos  = (const float*)d_in[0];   // [N,3] float32
    const float* mass = (const float*)d_in[1];   // [N]   float32
    float* out = (float*)d_out;                  // [N,3] float32

    const int n = in_sizes[0] / 3;               // 8192

    zero_out_kernel<<<(out_size + 255) / 256, 256>>>(out, out_size);

    dim3 grid(n / (BLOCK * IPT), n / JCHUNK);    // 32 x 32 = 1024 CTAs
    nbody_forces_kernel<<<grid, BLOCK>>>(pos, mass, out);
}